// round 7
// baseline (speedup 1.0000x reference)
#include <cuda_runtime.h>
#include <cstdint>

// Dynamic 5x5 per-pixel convolution + leaky_relu(0.2), replicate padding.
// x:      (N, C, H, W)    f32  -> 8 MB   (staged per CTA via cp.async)
// kernel: (N, C*25, H, W) f32  -> 200 MB (dominant HBM stream, read once)
// out:    (N, C, H, W)    f32  -> 8 MB
//
// R6: finer CTA granularity to balance work across SMs.
// 128-thread CTAs, 8-row strips, grid=1024, 8 CTAs/SM (single wave,
// 136 SMs x7 + 12 SMs x6 -> ~1% imbalance vs 25% at 512 CTAs).
// Keeps: cp.async stage, row-0 taps prefetched under the stage wait,
// double-buffered tap rows, streaming stores.

#define W_DIM 256
#define H_DIM 256
#define HW (W_DIM * H_DIM)
#define KS 5
#define PAD 2
#define ROWS_PER_CTA 8
#define ROWS_PER_THREAD 4
#define TILE_ROWS (ROWS_PER_CTA + 2 * PAD)   // 12
#define SROW 264                             // 256 + 2*PAD, padded
#define NTHREADS 128

__device__ __forceinline__ void cp_async4(uint32_t smem_addr, const float* gptr) {
    asm volatile("cp.async.ca.shared.global [%0], [%1], 4;"
                 :: "r"(smem_addr), "l"(gptr));
}

__global__ __launch_bounds__(NTHREADS, 8)
void dynconv5x5_kernel(const float* __restrict__ x,
                       const float* __restrict__ kern,
                       float* __restrict__ out)
{
    __shared__ float xs[TILE_ROWS][SROW];

    const int nc    = blockIdx.x >> 5;                   // plane index (0..31)
    const int hbase = (blockIdx.x & 31) * ROWS_PER_CTA;  // strip start row
    const int tx    = threadIdx.x;                       // 0..63 -> 4-px group
    const int ty    = threadIdx.y;                       // 0..1
    const int tid   = ty * 64 + tx;
    const int wbase = tx * 4;

    const float* xp    = x    + (size_t)nc * HW;
    const float* kpl   = kern + (size_t)nc * 25 * HW;
    float*       outpl = out  + (size_t)nc * HW;

    // ---- stage strip + halo via cp.async (replicate clamp at fill) ----
    uint32_t xs_base;
    asm("{ .reg .u64 t; cvta.to.shared.u64 t, %1; cvt.u32.u64 %0, t; }"
        : "=r"(xs_base) : "l"(&xs[0][0]));

    for (int idx = tid; idx < TILE_ROWS * SROW; idx += NTHREADS) {
        int r = idx / SROW;
        int c = idx - r * SROW;
        int gy = hbase + r - PAD;
        gy = gy < 0 ? 0 : (gy > H_DIM - 1 ? H_DIM - 1 : gy);
        int gx = c - PAD;
        gx = gx < 0 ? 0 : (gx > W_DIM - 1 ? W_DIM - 1 : gx);
        cp_async4(xs_base + (uint32_t)idx * 4u, xp + gy * W_DIM + gx);
    }
    asm volatile("cp.async.commit_group;");

    // ---- prefetch row-0 taps (rr=0) BEFORE the stage wait ----
    float4 kv[2][KS];
    {
        const int h0 = hbase + ty;
        const float* kb0 = kpl + (size_t)h0 * W_DIM + wbase;
        #pragma unroll
        for (int k2 = 0; k2 < KS; k2++)
            kv[0][k2] = __ldcs((const float4*)(kb0 + (size_t)k2 * HW));
    }

    asm volatile("cp.async.wait_group 0;");
    __syncthreads();   // the ONLY barrier

    // Each thread: rows hbase + ty + 2*rr, rr = 0..3
    #pragma unroll 1
    for (int rr = 0; rr < ROWS_PER_THREAD; rr++) {
        const int hloc = ty + rr * 2;            // row within strip (0..7)
        const int h    = hbase + hloc;           // global row
        const float* kbase = kpl + (size_t)h * W_DIM + wbase;

        if (rr > 0) {   // rr=0's kv[0] was preloaded under the stage wait
            #pragma unroll
            for (int k2 = 0; k2 < KS; k2++)
                kv[0][k2] = __ldcs((const float4*)(kbase + (size_t)k2 * HW));
        }

        float acc0 = 0.f, acc1 = 0.f, acc2 = 0.f, acc3 = 0.f;

        #pragma unroll
        for (int k1 = 0; k1 < KS; k1++) {
            const int cur = k1 & 1;
            if (k1 < KS - 1) {
                #pragma unroll
                for (int k2 = 0; k2 < KS; k2++)
                    kv[cur ^ 1][k2] =
                        __ldcs((const float4*)(kbase + (size_t)((k1 + 1) * KS + k2) * HW));
            }

            // 8-float sliding window from smem (aligned LDS.128 x2)
            float4 a = *(const float4*)&xs[hloc + k1][wbase];
            float4 b = *(const float4*)&xs[hloc + k1][wbase + 4];
            float r[8] = {a.x, a.y, a.z, a.w, b.x, b.y, b.z, b.w};

            #pragma unroll
            for (int k2 = 0; k2 < KS; k2++) {
                float4 c4 = kv[cur][k2];
                acc0 = fmaf(c4.x, r[k2 + 0], acc0);
                acc1 = fmaf(c4.y, r[k2 + 1], acc1);
                acc2 = fmaf(c4.z, r[k2 + 2], acc2);
                acc3 = fmaf(c4.w, r[k2 + 3], acc3);
            }
        }

        // leaky_relu(0.2) + streaming store of this row's 4 px
        acc0 = acc0 >= 0.f ? acc0 : 0.2f * acc0;
        acc1 = acc1 >= 0.f ? acc1 : 0.2f * acc1;
        acc2 = acc2 >= 0.f ? acc2 : 0.2f * acc2;
        acc3 = acc3 >= 0.f ? acc3 : 0.2f * acc3;

        __stcs((float4*)(outpl + (size_t)h * W_DIM + wbase),
               make_float4(acc0, acc1, acc2, acc3));
    }
}

extern "C" void kernel_launch(void* const* d_in, const int* in_sizes, int n_in,
                              void* d_out, int out_size)
{
    const float* x    = (const float*)d_in[0];
    const float* kern = (const float*)d_in[1];
    float* out        = (float*)d_out;

    const int NC = in_sizes[0] / HW;              // 32 for (4,8,256,256)

    dim3 block(64, 2);
    dim3 grid(NC * (H_DIM / ROWS_PER_CTA));       // 32 * 32 = 1024 CTAs
    dynconv5x5_kernel<<<grid, block>>>(x, kern, out);
}